// round 14
// baseline (speedup 1.0000x reference)
#include <cuda_runtime.h>

#define CH 512
#define LOG2E 1.4426950408889634f
#define NINT 20          // interpolation intervals
#define NNODE 23         // nodes: j=0..22, node j at s = qmin + (j-1)*h

__device__ __forceinline__ float ex2(float x) {
    float r;
    asm("ex2.approx.ftz.f32 %0, %1;" : "=f"(r) : "f"(x));
    return r;
}

// grid 256 (one batch/CTA), block 256, channels t and t+256 per thread
__global__ __launch_bounds__(256) void attn1d_kernel(
    const float* __restrict__ q, const float* __restrict__ k, const float* __restrict__ v,
    const float* __restrict__ wq, const float* __restrict__ wk, const float* __restrict__ wv,
    float* __restrict__ out)
{
    __shared__ float sq[CH + 4], sk[CH + 4], sv[CH + 4];
    __shared__ __align__(16) float skh[CH];   // khL = kh * log2e
    __shared__ __align__(16) float svv[CH];   // vh
    __shared__ float red[16];                 // 8 warps x {qmax, qmin}
    __shared__ float Rarr[NNODE + 1];

    const int b = blockIdx.x;
    const int t = threadIdx.x;
    const int warp = t >> 5, lane = t & 31;

    const float* qb = q + b * CH;
    const float* kb = k + b * CH;
    const float* vb = v + b * CH;

    // weights: float4 + scalar (2 LDGs per tensor instead of 5)
    const float4 wq4 = *(const float4*)wq;  const float wq5 = wq[4];
    const float4 wk4 = *(const float4*)wk;  const float wk5 = wk[4];
    const float4 wv4 = *(const float4*)wv;  const float wv5 = wv[4];
    const float Wq[5] = {wq4.x, wq4.y, wq4.z, wq4.w, wq5};
    const float Wk[5] = {wk4.x, wk4.y, wk4.z, wk4.w, wk5};
    const float Wv[5] = {wv4.x, wv4.y, wv4.z, wv4.w, wv5};

    if (t < 4) {
        const int i = (t < 2) ? t : (CH + t);  // 0,1,CH+2,CH+3
        sq[i] = 0.f; sk[i] = 0.f; sv[i] = 0.f;
    }
    sq[t + 2]   = qb[t];
    sq[t + 258] = qb[t + 256];
    sk[t + 2]   = kb[t];
    sk[t + 258] = kb[t + 256];
    sv[t + 2]   = vb[t];
    sv[t + 258] = vb[t + 256];
    __syncthreads();

    // convs: each thread does channels t and t+256
    float qmaxl = -1e30f, qminl = 1e30f;
    float s0 = 0.f, s1 = 0.f;
    #pragma unroll
    for (int h2 = 0; h2 < 2; h2++) {
        const int c = t + h2 * 256;
        float kh = 0.f, vh = 0.f, qh = 0.f;
        #pragma unroll
        for (int j = 0; j < 5; j++) {
            kh = fmaf(Wk[j], sk[c + j], kh);
            vh = fmaf(Wv[j], sv[c + j], vh);
            qh = fmaf(Wq[j], sq[c + j], qh);
        }
        skh[c] = kh * LOG2E;
        svv[c] = vh;
        qmaxl = fmaxf(qmaxl, qh);
        qminl = fminf(qminl, qh);
        if (h2 == 0) s0 = qh; else s1 = qh;
    }

    #pragma unroll
    for (int o = 16; o; o >>= 1) {
        qmaxl = fmaxf(qmaxl, __shfl_xor_sync(0xffffffffu, qmaxl, o));
        qminl = fminf(qminl, __shfl_xor_sync(0xffffffffu, qminl, o));
    }
    if (lane == 0) {
        red[warp * 2 + 0] = qmaxl;
        red[warp * 2 + 1] = qminl;
    }
    __syncthreads();   // publishes skh/svv AND red

    float qmax = red[0], qmin = red[1];
    #pragma unroll
    for (int i = 1; i < 8; i++) {
        qmax = fmaxf(qmax, red[i * 2 + 0]);
        qmin = fminf(qmin, red[i * 2 + 1]);
    }

    const float range = qmax - qmin;
    const bool  degen = !(range > 1e-30f);
    const float h     = degen ? 1.f : range * (1.f / NINT);
    const float inv_h = degen ? 0.f : (float)NINT / range;

    // ── node stage: ONE round, each warp owns nodes {w, w+8, w+16} (guarded) ──
    // no max-subtraction: |s*khL| small, exp2 stays in fp32 range;
    // num/den ratio is shift-invariant anyway.
    const float4* skh4 = (const float4*)skh;
    const float4* svv4 = (const float4*)svv;

    float sj[3], num[3], den[3];
    #pragma unroll
    for (int i = 0; i < 3; i++) {
        const int j = warp + 8 * i;            // j=23 (warp7,i=2) computed, not stored
        sj[i] = fmaf((float)(j - 1), h, qmin);
        num[i] = 0.f; den[i] = 0.f;
    }

    #pragma unroll
    for (int c4 = 0; c4 < 4; c4++) {
        const float4 xk = skh4[lane + 32 * c4];   // LDS.128, reused for 3 nodes
        const float4 xv = svv4[lane + 32 * c4];
        #pragma unroll
        for (int i = 0; i < 3; i++) {
            const float e0 = ex2(sj[i] * xk.x);
            const float e1 = ex2(sj[i] * xk.y);
            const float e2 = ex2(sj[i] * xk.z);
            const float e3 = ex2(sj[i] * xk.w);
            num[i] = fmaf(e0, xv.x, num[i]); den[i] += e0;
            num[i] = fmaf(e1, xv.y, num[i]); den[i] += e1;
            num[i] = fmaf(e2, xv.z, num[i]); den[i] += e2;
            num[i] = fmaf(e3, xv.w, num[i]); den[i] += e3;
        }
    }

    // 6 independent butterfly reductions, pipelined through the SHFL unit.
    // After a full butterfly ALL lanes hold the sums -> lanes 0/1/2 divide in parallel.
    #pragma unroll
    for (int o = 16; o; o >>= 1) {
        #pragma unroll
        for (int i = 0; i < 3; i++) {
            num[i] += __shfl_xor_sync(0xffffffffu, num[i], o);
            den[i] += __shfl_xor_sync(0xffffffffu, den[i], o);
        }
    }
    if (lane < 3) {
        const int j = warp + 8 * lane;
        if (j < NNODE) Rarr[j] = __fdividef(num[lane], den[lane]);
    }
    __syncthreads();

    // ── eval stage: cubic Lagrange through 4 nearest nodes ──
    #pragma unroll
    for (int h2 = 0; h2 < 2; h2++) {
        const float s = (h2 == 0) ? s0 : s1;
        float u = (s - qmin) * inv_h;
        u = fminf(fmaxf(u, 0.f), (float)NINT);
        int i = (int)u;
        i = min(i, NINT - 1);
        const float p = u - (float)i;          // in [0,1]
        // nodes at relative positions -1,0,1,2 -> Rarr[i..i+3]
        const float pm1 = p - 1.f, pm2 = p - 2.f, pp1 = p + 1.f;
        const float wm1 = -p * pm1 * pm2 * (1.f / 6.f);
        const float w0  =  pp1 * pm1 * pm2 * 0.5f;
        const float w1  = -pp1 * p * pm2 * 0.5f;
        const float w2  =  pp1 * p * pm1 * (1.f / 6.f);
        out[b * CH + t + h2 * 256] = wm1 * Rarr[i] + w0 * Rarr[i + 1]
                                   + w1 * Rarr[i + 2] + w2 * Rarr[i + 3];
    }
}

extern "C" void kernel_launch(void* const* d_in, const int* in_sizes, int n_in,
                              void* d_out, int out_size) {
    const float* q  = (const float*)d_in[0];
    const float* k  = (const float*)d_in[1];
    const float* v  = (const float*)d_in[2];
    const float* wq = (const float*)d_in[3];
    const float* wk = (const float*)d_in[4];
    const float* wv = (const float*)d_in[5];
    float* out = (float*)d_out;
    attn1d_kernel<<<256, 256>>>(q, k, v, wq, wk, wv, out);
}

// round 15
// speedup vs baseline: 1.1111x; 1.1111x over previous
#include <cuda_runtime.h>

#define CH 512
#define LOG2E 1.4426950408889634f
#define NINT 20          // interpolation intervals
#define NNODE 23         // nodes: j=0..22, node j at s = qmin + (j-1)*h

__device__ __forceinline__ float ex2(float x) {
    float r;
    asm("ex2.approx.ftz.f32 %0, %1;" : "=f"(r) : "f"(x));
    return r;
}

// grid 256 (one batch/CTA), block 256, channels t and t+256 per thread
__global__ __launch_bounds__(256) void attn1d_kernel(
    const float* __restrict__ q, const float* __restrict__ k, const float* __restrict__ v,
    const float* __restrict__ wq, const float* __restrict__ wk, const float* __restrict__ wv,
    float* __restrict__ out)
{
    __shared__ float sq[CH + 4], sk[CH + 4], sv[CH + 4];
    __shared__ __align__(16) float skh[CH];   // khL = kh * log2e
    __shared__ __align__(16) float svv[CH];   // vh
    __shared__ float red[16];                 // 8 warps x {qmax, qmin}
    __shared__ float Rarr[NNODE + 1];

    const int b = blockIdx.x;
    const int t = threadIdx.x;
    const int warp = t >> 5, lane = t & 31;

    const float* qb = q + b * CH;
    const float* kb = k + b * CH;
    const float* vb = v + b * CH;

    // weights: float4 + scalar (2 LDGs per tensor instead of 5)
    const float4 wq4 = *(const float4*)wq;  const float wq5 = wq[4];
    const float4 wk4 = *(const float4*)wk;  const float wk5 = wk[4];
    const float4 wv4 = *(const float4*)wv;  const float wv5 = wv[4];
    const float Wq[5] = {wq4.x, wq4.y, wq4.z, wq4.w, wq5};
    const float Wk[5] = {wk4.x, wk4.y, wk4.z, wk4.w, wk5};
    const float Wv[5] = {wv4.x, wv4.y, wv4.z, wv4.w, wv5};

    if (t < 4) {
        const int i = (t < 2) ? t : (CH + t);  // 0,1,CH+2,CH+3
        sq[i] = 0.f; sk[i] = 0.f; sv[i] = 0.f;
    }
    sq[t + 2]   = qb[t];
    sq[t + 258] = qb[t + 256];
    sk[t + 2]   = kb[t];
    sk[t + 258] = kb[t + 256];
    sv[t + 2]   = vb[t];
    sv[t + 258] = vb[t + 256];
    __syncthreads();

    // convs: each thread does channels t and t+256
    float qmaxl = -1e30f, qminl = 1e30f;
    float s0 = 0.f, s1 = 0.f;
    #pragma unroll
    for (int h2 = 0; h2 < 2; h2++) {
        const int c = t + h2 * 256;
        float kh = 0.f, vh = 0.f, qh = 0.f;
        #pragma unroll
        for (int j = 0; j < 5; j++) {
            kh = fmaf(Wk[j], sk[c + j], kh);
            vh = fmaf(Wv[j], sv[c + j], vh);
            qh = fmaf(Wq[j], sq[c + j], qh);
        }
        skh[c] = kh * LOG2E;
        svv[c] = vh;
        qmaxl = fmaxf(qmaxl, qh);
        qminl = fminf(qminl, qh);
        if (h2 == 0) s0 = qh; else s1 = qh;
    }

    #pragma unroll
    for (int o = 16; o; o >>= 1) {
        qmaxl = fmaxf(qmaxl, __shfl_xor_sync(0xffffffffu, qmaxl, o));
        qminl = fminf(qminl, __shfl_xor_sync(0xffffffffu, qminl, o));
    }
    if (lane == 0) {
        red[warp * 2 + 0] = qmaxl;
        red[warp * 2 + 1] = qminl;
    }
    __syncthreads();   // publishes skh/svv AND red

    float qmax = red[0], qmin = red[1];
    #pragma unroll
    for (int i = 1; i < 8; i++) {
        qmax = fmaxf(qmax, red[i * 2 + 0]);
        qmin = fminf(qmin, red[i * 2 + 1]);
    }

    const float range = qmax - qmin;
    const bool  degen = !(range > 1e-30f);
    const float h     = degen ? 1.f : range * (1.f / NINT);
    const float inv_h = degen ? 0.f : (float)NINT / range;

    // ── node stage: ONE round, each warp owns nodes {w, w+8, w+16} ──
    // no max-subtraction: |s*khL| small, exp2 stays in fp32 range;
    // num/den ratio is shift-invariant anyway.
    const float4* skh4 = (const float4*)skh;
    const float4* svv4 = (const float4*)svv;

    float sj[3], num[3], den[3];
    #pragma unroll
    for (int i = 0; i < 3; i++) {
        const int j = warp + 8 * i;            // j=23 (warp7,i=2) computed, not stored
        sj[i] = fmaf((float)(j - 1), h, qmin);
        num[i] = 0.f; den[i] = 0.f;
    }

    #pragma unroll
    for (int c4 = 0; c4 < 4; c4++) {
        const float4 xk = skh4[lane + 32 * c4];   // LDS.128 broadcast, reused x3
        const float4 xv = svv4[lane + 32 * c4];
        #pragma unroll
        for (int i = 0; i < 3; i++) {
            const float e0 = ex2(sj[i] * xk.x);
            const float e1 = ex2(sj[i] * xk.y);
            const float e2 = ex2(sj[i] * xk.z);
            const float e3 = ex2(sj[i] * xk.w);
            num[i] = fmaf(e0, xv.x, num[i]); den[i] += e0;
            num[i] = fmaf(e1, xv.y, num[i]); den[i] += e1;
            num[i] = fmaf(e2, xv.z, num[i]); den[i] += e2;
            num[i] = fmaf(e3, xv.w, num[i]); den[i] += e3;
        }
    }

    // 6 independent butterfly reductions, pipelined through the SHFL unit.
    // After a full butterfly ALL lanes hold the sums -> lanes 0/1/2 divide in parallel.
    #pragma unroll
    for (int o = 16; o; o >>= 1) {
        #pragma unroll
        for (int i = 0; i < 3; i++) {
            num[i] += __shfl_xor_sync(0xffffffffu, num[i], o);
            den[i] += __shfl_xor_sync(0xffffffffu, den[i], o);
        }
    }
    {
        const int j = warp + 8 * lane;         // lane<3 -> node index
        if (lane < 3 && j < NNODE)
            Rarr[j] = __fdividef(num[lane], den[lane]);
    }
    __syncthreads();

    // ── eval stage: cubic Lagrange through 4 nearest nodes ──
    #pragma unroll
    for (int h2 = 0; h2 < 2; h2++) {
        const float s = (h2 == 0) ? s0 : s1;
        float u = (s - qmin) * inv_h;
        u = fminf(fmaxf(u, 0.f), (float)NINT);
        int i = (int)u;
        i = min(i, NINT - 1);
        const float p = u - (float)i;          // in [0,1]
        // nodes at relative positions -1,0,1,2 -> Rarr[i..i+3]
        const float pm1 = p - 1.f, pm2 = p - 2.f, pp1 = p + 1.f;
        const float wm1 = -p * pm1 * pm2 * (1.f / 6.f);
        const float w0  =  pp1 * pm1 * pm2 * 0.5f;
        const float w1  = -pp1 * p * pm2 * 0.5f;
        const float w2  =  pp1 * p * pm1 * (1.f / 6.f);
        out[b * CH + t + h2 * 256] = wm1 * Rarr[i] + w0 * Rarr[i + 1]
                                   + w1 * Rarr[i + 2] + w2 * Rarr[i + 3];
    }
}

extern "C" void kernel_launch(void* const* d_in, const int* in_sizes, int n_in,
                              void* d_out, int out_size) {
    const float* q  = (const float*)d_in[0];
    const float* k  = (const float*)d_in[1];
    const float* v  = (const float*)d_in[2];
    const float* wq = (const float*)d_in[3];
    const float* wk = (const float*)d_in[4];
    const float* wv = (const float*)d_in[5];
    float* out = (float*)d_out;
    attn1d_kernel<<<256, 256>>>(q, k, v, wq, wk, wv, out);
}